// round 3
// baseline (speedup 1.0000x reference)
#include <cuda_runtime.h>
#include <cuda_bf16.h>
#include <cstdint>

#define TSTEPS 8192
#define NN     1024

// Scratch (device globals; no allocation allowed in kernel_launch)
__device__ float g_I[(size_t)TSTEPS * NN];   // I_all = X @ W1^T, [T, N]
__device__ float g_S[TSTEPS];                // per-step weighted spike sum

// ---------------------------------------------------------------------------
// Kernel 1: C = A * B^T   (A: MxK row-major, B: NxK row-major, C: MxN)
// M=8192, N=1024, K=1024, all multiples of tile sizes -> no bounds checks.
// 128x128 block tile, K-tile 16, 256 threads, 8x8 per-thread microtile,
// double-buffered shared memory.
// ---------------------------------------------------------------------------
__global__ __launch_bounds__(256)
void gemm_nt_kernel(const float* __restrict__ A, const float* __restrict__ B,
                    int M, int N, int K)
{
    constexpr int TM = 128, TN = 128, TK = 16;
    __shared__ float As[2][TK][TM + 4];
    __shared__ float Bs[2][TK][TN + 4];

    const int tid = threadIdx.x;
    const int bm = blockIdx.y * TM;
    const int bn = blockIdx.x * TN;

    // loader mapping: rows lr and lr+64, k-offset lk (float4 granularity)
    const int lr = tid >> 2;            // 0..63
    const int lk = (tid & 3) * 4;       // 0,4,8,12

    const float* Ag = A + (size_t)(bm + lr) * K + lk;
    const float* Bg = B + (size_t)(bn + lr) * K + lk;

    // compute mapping: 16x16 thread grid, 8x8 outputs each
    const int tm = (tid >> 4) * 8;
    const int tn = (tid & 15) * 8;

    float acc[8][8];
#pragma unroll
    for (int i = 0; i < 8; i++)
#pragma unroll
        for (int j = 0; j < 8; j++) acc[i][j] = 0.f;

    // prologue: load K-tile 0
    {
        float4 a0 = *(const float4*)(Ag);
        float4 a1 = *(const float4*)(Ag + (size_t)64 * K);
        float4 b0 = *(const float4*)(Bg);
        float4 b1 = *(const float4*)(Bg + (size_t)64 * K);
        As[0][lk + 0][lr]      = a0.x; As[0][lk + 1][lr]      = a0.y;
        As[0][lk + 2][lr]      = a0.z; As[0][lk + 3][lr]      = a0.w;
        As[0][lk + 0][lr + 64] = a1.x; As[0][lk + 1][lr + 64] = a1.y;
        As[0][lk + 2][lr + 64] = a1.z; As[0][lk + 3][lr + 64] = a1.w;
        Bs[0][lk + 0][lr]      = b0.x; Bs[0][lk + 1][lr]      = b0.y;
        Bs[0][lk + 2][lr]      = b0.z; Bs[0][lk + 3][lr]      = b0.w;
        Bs[0][lk + 0][lr + 64] = b1.x; Bs[0][lk + 1][lr + 64] = b1.y;
        Bs[0][lk + 2][lr + 64] = b1.z; Bs[0][lk + 3][lr + 64] = b1.w;
    }
    __syncthreads();

    int buf = 0;
#pragma unroll 1
    for (int kt = TK; kt <= K; kt += TK) {
        const bool last = (kt == K);
        float4 na0, na1, nb0, nb1;
        if (!last) {
            na0 = *(const float4*)(Ag + kt);
            na1 = *(const float4*)(Ag + (size_t)64 * K + kt);
            nb0 = *(const float4*)(Bg + kt);
            nb1 = *(const float4*)(Bg + (size_t)64 * K + kt);
        }

#pragma unroll
        for (int k = 0; k < TK; k++) {
            float4 af0 = *(const float4*)&As[buf][k][tm];
            float4 af1 = *(const float4*)&As[buf][k][tm + 4];
            float4 bf0 = *(const float4*)&Bs[buf][k][tn];
            float4 bf1 = *(const float4*)&Bs[buf][k][tn + 4];
            float ar[8] = {af0.x, af0.y, af0.z, af0.w, af1.x, af1.y, af1.z, af1.w};
            float br[8] = {bf0.x, bf0.y, bf0.z, bf0.w, bf1.x, bf1.y, bf1.z, bf1.w};
#pragma unroll
            for (int i = 0; i < 8; i++)
#pragma unroll
                for (int j = 0; j < 8; j++)
                    acc[i][j] = fmaf(ar[i], br[j], acc[i][j]);
        }

        if (!last) {
            const int nb = buf ^ 1;
            As[nb][lk + 0][lr]      = na0.x; As[nb][lk + 1][lr]      = na0.y;
            As[nb][lk + 2][lr]      = na0.z; As[nb][lk + 3][lr]      = na0.w;
            As[nb][lk + 0][lr + 64] = na1.x; As[nb][lk + 1][lr + 64] = na1.y;
            As[nb][lk + 2][lr + 64] = na1.z; As[nb][lk + 3][lr + 64] = na1.w;
            Bs[nb][lk + 0][lr]      = nb0.x; Bs[nb][lk + 1][lr]      = nb0.y;
            Bs[nb][lk + 2][lr]      = nb0.z; Bs[nb][lk + 3][lr]      = nb0.w;
            Bs[nb][lk + 0][lr + 64] = nb1.x; Bs[nb][lk + 1][lr + 64] = nb1.y;
            Bs[nb][lk + 2][lr + 64] = nb1.z; Bs[nb][lk + 3][lr + 64] = nb1.w;
            __syncthreads();
            buf = nb;
        }
    }

    // epilogue: write to g_I
#pragma unroll
    for (int i = 0; i < 8; i++) {
        float* Cr = g_I + (size_t)(bm + tm + i) * N + bn + tn;
        *(float4*)(Cr)     = make_float4(acc[i][0], acc[i][1], acc[i][2], acc[i][3]);
        *(float4*)(Cr + 4) = make_float4(acc[i][4], acc[i][5], acc[i][6], acc[i][7]);
    }
}

// ---------------------------------------------------------------------------
// Kernel 2: per-neuron serial Izhikevich scan. One thread per neuron.
// ---------------------------------------------------------------------------
__global__ __launch_bounds__(128)
void scan_kernel(const float* __restrict__ st0,
                 const float* __restrict__ a_, const float* __restrict__ b_,
                 const float* __restrict__ c_, const float* __restrict__ d_,
                 const float* __restrict__ th_, const float* __restrict__ dt_,
                 float* __restrict__ spikes, float* __restrict__ states)
{
    const int n = blockIdx.x * blockDim.x + threadIdx.x;   // 0..1023
    float v = st0[n];
    float u = st0[NN + n];
    const float an  = a_[n],  bn  = b_[n];
    const float cn  = c_[n],  dn  = d_[n];
    const float thn = th_[n], dtn = dt_[n];
    const float dta = dtn * an;   // matches reference association (dt*a)*(b*v-u)

    const float* Ip = g_I + n;
    float* sp = spikes + n;
    float* vp = states + n;
    float* up = states + NN + n;

    constexpr int PF = 8;
    float pf[PF];
#pragma unroll
    for (int i = 0; i < PF; i++) pf[i] = Ip[(size_t)i * NN];

#pragma unroll 8
    for (int t = 0; t < TSTEPS; t++) {
        const float In = pf[0];
#pragma unroll
        for (int i = 0; i < PF - 1; i++) pf[i] = pf[i + 1];
        int tp = t + PF; if (tp > TSTEPS - 1) tp = TSTEPS - 1;
        pf[PF - 1] = Ip[(size_t)tp * NN];

        // Izhikevich Euler step (reference association)
        const float poly = 0.04f * v * v + 5.0f * v + 140.0f - u + In;
        const float vn = v + dtn * poly;
        const float un = u + dta * (bn * v - u);
        const bool  fired = (vn > thn);
        const float s = fired ? 1.0f : 0.0f;
        v = fired ? cn : vn;          // exact: vn*(1-s)+c*s for s in {0,1}
        u = un + dn * s;

        sp[(size_t)t * NN]        = s;
        vp[(size_t)t * 2 * NN]    = v;
        up[(size_t)t * 2 * NN]    = u;
    }
}

// ---------------------------------------------------------------------------
// Kernel 3: S[t] = sum_n W2[n] * spikes[t,n]   (one block per timestep)
// ---------------------------------------------------------------------------
__global__ __launch_bounds__(256)
void rowsum_kernel(const float* __restrict__ spikes, const float* __restrict__ w2)
{
    const int t = blockIdx.x;
    const int tid = threadIdx.x;   // 256 threads * float4 = 1024 elems
    const float4 sv = ((const float4*)(spikes + (size_t)t * NN))[tid];
    const float4 wv = ((const float4*)w2)[tid];
    float sum = sv.x * wv.x + sv.y * wv.y + sv.z * wv.z + sv.w * wv.w;

#pragma unroll
    for (int o = 16; o > 0; o >>= 1)
        sum += __shfl_xor_sync(0xffffffffu, sum, o);

    __shared__ float ws[8];
    if ((tid & 31) == 0) ws[tid >> 5] = sum;
    __syncthreads();
    if (tid < 8) {
        float x = ws[tid];
#pragma unroll
        for (int o = 4; o > 0; o >>= 1)
            x += __shfl_xor_sync(0xffu, x, o);
        if (tid == 0) g_S[t] = x;
    }
}

// ---------------------------------------------------------------------------
// Kernel 4: decode scan dm[t] = leak*dm[t-1] + S[t]  (serial, cheap)
// ---------------------------------------------------------------------------
__global__ void decode_kernel(const float* __restrict__ leak,
                              float* __restrict__ decoded)
{
    if (threadIdx.x == 0) {
        const float L = leak[0];
        float dm = 0.f;
        for (int t = 0; t < TSTEPS; t++) {
            dm = L * dm + g_S[t];
            decoded[t] = dm;
        }
    }
}

// ---------------------------------------------------------------------------
extern "C" void kernel_launch(void* const* d_in, const int* in_sizes, int n_in,
                              void* d_out, int out_size)
{
    const float* X    = (const float*)d_in[0];   // [T, N]
    const float* st0  = (const float*)d_in[1];   // [2, N]
    const float* W1   = (const float*)d_in[2];   // [N, N]
    const float* W2   = (const float*)d_in[3];   // [1, N]
    const float* a    = (const float*)d_in[4];
    const float* b    = (const float*)d_in[5];
    const float* c    = (const float*)d_in[6];
    const float* d    = (const float*)d_in[7];
    const float* th   = (const float*)d_in[8];
    const float* dt   = (const float*)d_in[9];
    const float* leak = (const float*)d_in[10];

    float* out     = (float*)d_out;
    float* spikes  = out;                                       // [T, N]
    float* states  = out + (size_t)TSTEPS * NN;                 // [T, 2, N]
    float* decoded = out + (size_t)TSTEPS * NN * 3;             // [T, 1]

    // 1) I_all = X @ W1^T
    dim3 ggrid(NN / 128, TSTEPS / 128);
    gemm_nt_kernel<<<ggrid, 256>>>(X, W1, TSTEPS, NN, NN);

    // 2) per-neuron scan
    scan_kernel<<<8, 128>>>(st0, a, b, c, d, th, dt, spikes, states);

    // 3) per-step weighted spike sums
    rowsum_kernel<<<TSTEPS, 256>>>(spikes, W2);

    // 4) decode leaky integrator
    decode_kernel<<<1, 32>>>(leak, decoded);
}

// round 4
// speedup vs baseline: 1.2436x; 1.2436x over previous
#include <cuda_runtime.h>
#include <cuda_bf16.h>
#include <cstdint>

#define TSTEPS 8192
#define NN     1024

// Scratch (device globals; no allocation allowed in kernel_launch)
__device__ float g_I[(size_t)TSTEPS * NN];   // I_all = X @ W1^T, [T, N]
__device__ float g_S[TSTEPS];                // per-step weighted spike sum

// ---------------------------------------------------------------------------
// Packed fp32x2 helpers (Blackwell FFMA2 — not emitted by ptxas from C++)
// ---------------------------------------------------------------------------
__device__ __forceinline__ unsigned long long pack_dup(float x) {
    unsigned long long r;
    asm("mov.b64 %0, {%1, %1};" : "=l"(r) : "f"(x));
    return r;
}
__device__ __forceinline__ void ffma2(unsigned long long& d,
                                      unsigned long long a,
                                      unsigned long long b) {
    asm("fma.rn.f32x2 %0, %1, %2, %0;" : "+l"(d) : "l"(a), "l"(b));
}

// ---------------------------------------------------------------------------
// Kernel 1: C = A * B^T   (A: MxK row-major, B: NxK row-major, C: MxN)
// 128x128 block tile, K-tile 16, 256 threads, 8x8 per-thread microtile
// computed as 8x4 packed f32x2 pairs (FFMA2), double-buffered smem.
// ---------------------------------------------------------------------------
__global__ __launch_bounds__(256, 2)
void gemm_nt_kernel(const float* __restrict__ A, const float* __restrict__ B,
                    int M, int N, int K)
{
    constexpr int TM = 128, TN = 128, TK = 16;
    __shared__ float As[2][TK][TM + 4];
    __shared__ float Bs[2][TK][TN + 4];

    const int tid = threadIdx.x;
    const int bm = blockIdx.y * TM;
    const int bn = blockIdx.x * TN;

    // loader mapping: rows lr and lr+64, k-offset lk (float4 granularity)
    const int lr = tid >> 2;            // 0..63
    const int lk = (tid & 3) * 4;       // 0,4,8,12

    const float* Ag = A + (size_t)(bm + lr) * K + lk;
    const float* Bg = B + (size_t)(bn + lr) * K + lk;

    // compute mapping: 16x16 thread grid, 8x8 outputs each
    const int tm = (tid >> 4) * 8;
    const int tn = (tid & 15) * 8;

    // acc[i][j] holds columns (tn+2j, tn+2j+1) of row (tm+i), packed f32x2
    unsigned long long acc[8][4];
#pragma unroll
    for (int i = 0; i < 8; i++)
#pragma unroll
        for (int j = 0; j < 4; j++) acc[i][j] = 0ull;  // two packed 0.0f

    // prologue: load K-tile 0
    {
        float4 a0 = *(const float4*)(Ag);
        float4 a1 = *(const float4*)(Ag + (size_t)64 * K);
        float4 b0 = *(const float4*)(Bg);
        float4 b1 = *(const float4*)(Bg + (size_t)64 * K);
        As[0][lk + 0][lr]      = a0.x; As[0][lk + 1][lr]      = a0.y;
        As[0][lk + 2][lr]      = a0.z; As[0][lk + 3][lr]      = a0.w;
        As[0][lk + 0][lr + 64] = a1.x; As[0][lk + 1][lr + 64] = a1.y;
        As[0][lk + 2][lr + 64] = a1.z; As[0][lk + 3][lr + 64] = a1.w;
        Bs[0][lk + 0][lr]      = b0.x; Bs[0][lk + 1][lr]      = b0.y;
        Bs[0][lk + 2][lr]      = b0.z; Bs[0][lk + 3][lr]      = b0.w;
        Bs[0][lk + 0][lr + 64] = b1.x; Bs[0][lk + 1][lr + 64] = b1.y;
        Bs[0][lk + 2][lr + 64] = b1.z; Bs[0][lk + 3][lr + 64] = b1.w;
    }
    __syncthreads();

    int buf = 0;
#pragma unroll 1
    for (int kt = TK; kt <= K; kt += TK) {
        const bool last = (kt == K);
        float4 na0, na1, nb0, nb1;
        if (!last) {
            na0 = *(const float4*)(Ag + kt);
            na1 = *(const float4*)(Ag + (size_t)64 * K + kt);
            nb0 = *(const float4*)(Bg + kt);
            nb1 = *(const float4*)(Bg + (size_t)64 * K + kt);
        }

#pragma unroll
        for (int k = 0; k < TK; k++) {
            float4 af0 = *(const float4*)&As[buf][k][tm];
            float4 af1 = *(const float4*)&As[buf][k][tm + 4];
            // B pairs come straight out of LDS.128 as adjacent register pairs
            ulonglong2 bq0 = *(const ulonglong2*)&Bs[buf][k][tn];
            ulonglong2 bq1 = *(const ulonglong2*)&Bs[buf][k][tn + 4];
            unsigned long long br[4] = {bq0.x, bq0.y, bq1.x, bq1.y};
            float ar[8] = {af0.x, af0.y, af0.z, af0.w,
                           af1.x, af1.y, af1.z, af1.w};
#pragma unroll
            for (int i = 0; i < 8; i++) {
                const unsigned long long ad = pack_dup(ar[i]);
#pragma unroll
                for (int j = 0; j < 4; j++)
                    ffma2(acc[i][j], ad, br[j]);
            }
        }

        if (!last) {
            const int nb = buf ^ 1;
            As[nb][lk + 0][lr]      = na0.x; As[nb][lk + 1][lr]      = na0.y;
            As[nb][lk + 2][lr]      = na0.z; As[nb][lk + 3][lr]      = na0.w;
            As[nb][lk + 0][lr + 64] = na1.x; As[nb][lk + 1][lr + 64] = na1.y;
            As[nb][lk + 2][lr + 64] = na1.z; As[nb][lk + 3][lr + 64] = na1.w;
            Bs[nb][lk + 0][lr]      = nb0.x; Bs[nb][lk + 1][lr]      = nb0.y;
            Bs[nb][lk + 2][lr]      = nb0.z; Bs[nb][lk + 3][lr]      = nb0.w;
            Bs[nb][lk + 0][lr + 64] = nb1.x; Bs[nb][lk + 1][lr + 64] = nb1.y;
            Bs[nb][lk + 2][lr + 64] = nb1.z; Bs[nb][lk + 3][lr + 64] = nb1.w;
            __syncthreads();
            buf = nb;
        }
    }

    // epilogue: packed pairs are already the row-major layout; STG.128
#pragma unroll
    for (int i = 0; i < 8; i++) {
        float* Cr = g_I + (size_t)(bm + tm + i) * N + bn + tn;
        ulonglong2 w0; w0.x = acc[i][0]; w0.y = acc[i][1];
        ulonglong2 w1; w1.x = acc[i][2]; w1.y = acc[i][3];
        *(ulonglong2*)(Cr)     = w0;
        *(ulonglong2*)(Cr + 4) = w1;
    }
}

// ---------------------------------------------------------------------------
// Kernel 2: per-neuron serial Izhikevich scan. Two neurons per thread
// (adjacent n -> float2 loads/stores), 512 threads total.
// ---------------------------------------------------------------------------
__global__ __launch_bounds__(128)
void scan_kernel(const float* __restrict__ st0,
                 const float* __restrict__ a_, const float* __restrict__ b_,
                 const float* __restrict__ c_, const float* __restrict__ d_,
                 const float* __restrict__ th_, const float* __restrict__ dt_,
                 float* __restrict__ spikes, float* __restrict__ states)
{
    const int p = blockIdx.x * blockDim.x + threadIdx.x;   // 0..511
    const int n = 2 * p;

    float v0 = st0[n],      v1 = st0[n + 1];
    float u0 = st0[NN + n], u1 = st0[NN + n + 1];
    const float2 aa = *(const float2*)(a_  + n);
    const float2 bb = *(const float2*)(b_  + n);
    const float2 cc = *(const float2*)(c_  + n);
    const float2 dd = *(const float2*)(d_  + n);
    const float2 th = *(const float2*)(th_ + n);
    const float2 dt = *(const float2*)(dt_ + n);
    const float dta0 = dt.x * aa.x;   // matches reference (dt*a)*(b*v-u)
    const float dta1 = dt.y * aa.y;

    const float2* Ip = (const float2*)g_I + p;      // row stride NN/2
    float2* sp = (float2*)spikes + p;               // row stride NN/2
    float2* vp = (float2*)states + p;               // row stride NN
    float2* up = (float2*)states + (NN / 2) + p;

    constexpr int PF = 8;
    float2 pf[PF];
#pragma unroll
    for (int i = 0; i < PF; i++) pf[i] = Ip[(size_t)i * (NN / 2)];

#pragma unroll 8
    for (int t = 0; t < TSTEPS - PF; t++) {
        const float2 In = pf[0];
#pragma unroll
        for (int i = 0; i < PF - 1; i++) pf[i] = pf[i + 1];
        pf[PF - 1] = Ip[(size_t)(t + PF) * (NN / 2)];

        // neuron 0
        const float poly0 = 0.04f * v0 * v0 + 5.0f * v0 + 140.0f - u0 + In.x;
        const float vn0 = v0 + dt.x * poly0;
        const float un0 = u0 + dta0 * (bb.x * v0 - u0);
        const bool f0 = (vn0 > th.x);
        // neuron 1
        const float poly1 = 0.04f * v1 * v1 + 5.0f * v1 + 140.0f - u1 + In.y;
        const float vn1 = v1 + dt.y * poly1;
        const float un1 = u1 + dta1 * (bb.y * v1 - u1);
        const bool f1 = (vn1 > th.y);

        v0 = f0 ? cc.x : vn0;  u0 = f0 ? (un0 + dd.x) : un0;
        v1 = f1 ? cc.y : vn1;  u1 = f1 ? (un1 + dd.y) : un1;

        sp[(size_t)t * (NN / 2)] = make_float2(f0 ? 1.f : 0.f, f1 ? 1.f : 0.f);
        vp[(size_t)t * NN]       = make_float2(v0, v1);
        up[(size_t)t * NN]       = make_float2(u0, u1);
    }

    // tail: last PF steps from the prefetch registers
#pragma unroll
    for (int k = 0; k < PF; k++) {
        const int t = TSTEPS - PF + k;
        const float2 In = pf[k];
        const float poly0 = 0.04f * v0 * v0 + 5.0f * v0 + 140.0f - u0 + In.x;
        const float vn0 = v0 + dt.x * poly0;
        const float un0 = u0 + dta0 * (bb.x * v0 - u0);
        const bool f0 = (vn0 > th.x);
        const float poly1 = 0.04f * v1 * v1 + 5.0f * v1 + 140.0f - u1 + In.y;
        const float vn1 = v1 + dt.y * poly1;
        const float un1 = u1 + dta1 * (bb.y * v1 - u1);
        const bool f1 = (vn1 > th.y);
        v0 = f0 ? cc.x : vn0;  u0 = f0 ? (un0 + dd.x) : un0;
        v1 = f1 ? cc.y : vn1;  u1 = f1 ? (un1 + dd.y) : un1;
        sp[(size_t)t * (NN / 2)] = make_float2(f0 ? 1.f : 0.f, f1 ? 1.f : 0.f);
        vp[(size_t)t * NN]       = make_float2(v0, v1);
        up[(size_t)t * NN]       = make_float2(u0, u1);
    }
}

// ---------------------------------------------------------------------------
// Kernel 3: S[t] = sum_n W2[n] * spikes[t,n]   (one block per timestep)
// ---------------------------------------------------------------------------
__global__ __launch_bounds__(256)
void rowsum_kernel(const float* __restrict__ spikes, const float* __restrict__ w2)
{
    const int t = blockIdx.x;
    const int tid = threadIdx.x;   // 256 threads * float4 = 1024 elems
    const float4 sv = ((const float4*)(spikes + (size_t)t * NN))[tid];
    const float4 wv = ((const float4*)w2)[tid];
    float sum = sv.x * wv.x + sv.y * wv.y + sv.z * wv.z + sv.w * wv.w;

#pragma unroll
    for (int o = 16; o > 0; o >>= 1)
        sum += __shfl_xor_sync(0xffffffffu, sum, o);

    __shared__ float ws[8];
    if ((tid & 31) == 0) ws[tid >> 5] = sum;
    __syncthreads();
    if (tid < 8) {
        float x = ws[tid];
#pragma unroll
        for (int o = 4; o > 0; o >>= 1)
            x += __shfl_xor_sync(0xffu, x, o);
        if (tid == 0) g_S[t] = x;
    }
}

// ---------------------------------------------------------------------------
// Kernel 4: parallel decode scan.  dm[t] = L*dm[t-1] + S[t]
// Chunk of 8 per thread -> affine (scale, offset); Hillis-Steele composition
// over 1024 threads; replay chunk with incoming carry.
// ---------------------------------------------------------------------------
__global__ __launch_bounds__(1024)
void decode_scan_kernel(const float* __restrict__ leak,
                        float* __restrict__ decoded)
{
    constexpr int C = TSTEPS / 1024;   // 8
    __shared__ float s_scale[1024];
    __shared__ float s_off[1024];

    const int tid = threadIdx.x;
    const float L = leak[0];
    const int base = tid * C;

    float vals[C];
#pragma unroll
    for (int k = 0; k < C; k++) vals[k] = g_S[base + k];

    // local chunk applied to 0 -> offset; scale = L^C
    float dm = 0.f;
#pragma unroll
    for (int k = 0; k < C; k++) dm = L * dm + vals[k];
    float L2 = L * L, L4 = L2 * L2, L8 = L4 * L4;

    float myS = L8, myO = dm;
    s_scale[tid] = myS; s_off[tid] = myO;
    __syncthreads();

    // inclusive scan of affine composition: new[i] = cur[i] o cur[i-d]
    for (int d = 1; d < 1024; d <<= 1) {
        float ps = 1.f, po = 0.f;
        if (tid >= d) { ps = s_scale[tid - d]; po = s_off[tid - d]; }
        __syncthreads();
        myO = myS * po + myO;
        myS = myS * ps;
        s_scale[tid] = myS; s_off[tid] = myO;
        __syncthreads();
    }

    const float carry_in = (tid == 0) ? 0.f : s_off[tid - 1];

    dm = carry_in;
#pragma unroll
    for (int k = 0; k < C; k++) {
        dm = L * dm + vals[k];
        decoded[base + k] = dm;
    }
}

// ---------------------------------------------------------------------------
extern "C" void kernel_launch(void* const* d_in, const int* in_sizes, int n_in,
                              void* d_out, int out_size)
{
    const float* X    = (const float*)d_in[0];   // [T, N]
    const float* st0  = (const float*)d_in[1];   // [2, N]
    const float* W1   = (const float*)d_in[2];   // [N, N]
    const float* W2   = (const float*)d_in[3];   // [1, N]
    const float* a    = (const float*)d_in[4];
    const float* b    = (const float*)d_in[5];
    const float* c    = (const float*)d_in[6];
    const float* d    = (const float*)d_in[7];
    const float* th   = (const float*)d_in[8];
    const float* dt   = (const float*)d_in[9];
    const float* leak = (const float*)d_in[10];

    float* out     = (float*)d_out;
    float* spikes  = out;                                       // [T, N]
    float* states  = out + (size_t)TSTEPS * NN;                 // [T, 2, N]
    float* decoded = out + (size_t)TSTEPS * NN * 3;             // [T, 1]

    // 1) I_all = X @ W1^T  (FFMA2 packed fp32)
    dim3 ggrid(NN / 128, TSTEPS / 128);
    gemm_nt_kernel<<<ggrid, 256>>>(X, W1, TSTEPS, NN, NN);

    // 2) per-neuron scan (2 neurons per thread)
    scan_kernel<<<4, 128>>>(st0, a, b, c, d, th, dt, spikes, states);

    // 3) per-step weighted spike sums
    rowsum_kernel<<<TSTEPS, 256>>>(spikes, W2);

    // 4) decode leaky integrator (parallel affine scan)
    decode_scan_kernel<<<1, 1024>>>(leak, decoded);
}

// round 7
// speedup vs baseline: 1.7623x; 1.4172x over previous
#include <cuda_runtime.h>
#include <cuda_bf16.h>
#include <cstdint>

#define TSTEPS 8192
#define NN     1024

// Scratch (device globals; no allocation allowed in kernel_launch)
__device__ float g_I[(size_t)TSTEPS * NN];   // dense fallback: I_all = X @ W1^T
__device__ float g_S[TSTEPS];                // per-step weighted spike sum
__device__ int   g_cnt[NN];                  // nonzeros per W1 row
__device__ int   g_col[NN];                  // col of the single nonzero (if nnz<=1)
__device__ float g_val[NN];                  // val of the single nonzero
__device__ int   g_maxnnz;                   // max row nnz; <=1 -> sparse fast path

// ---------------------------------------------------------------------------
// Packed fp32x2 helpers (Blackwell FFMA2)
// ---------------------------------------------------------------------------
__device__ __forceinline__ unsigned long long pack_dup(float x) {
    unsigned long long r;
    asm("mov.b64 %0, {%1, %1};" : "=l"(r) : "f"(x));
    return r;
}
__device__ __forceinline__ void ffma2(unsigned long long& d,
                                      unsigned long long a,
                                      unsigned long long b) {
    asm("fma.rn.f32x2 %0, %1, %2, %0;" : "+l"(d) : "l"(a), "l"(b));
}

// ---------------------------------------------------------------------------
// Kernel 0a: analyze W1 sparsity. One warp per row.
// ---------------------------------------------------------------------------
__global__ __launch_bounds__(256)
void analyze_kernel(const float* __restrict__ W1)
{
    const int warp = (blockIdx.x * blockDim.x + threadIdx.x) >> 5;
    const int lane = threadIdx.x & 31;
    if (warp >= NN) return;
    const float* row = W1 + (size_t)warp * NN;

    int   cnt = 0, col = 0;
    float val = 0.f;
#pragma unroll 4
    for (int c = lane; c < NN; c += 32) {
        float w = row[c];
        if (w != 0.f) { cnt++; col = c; val = w; }
    }
    // total count
    int total = cnt;
#pragma unroll
    for (int o = 16; o > 0; o >>= 1)
        total += __shfl_xor_sync(0xffffffffu, total, o);
    // pick (col,val) from the first lane that has a nonzero
    unsigned mask = __ballot_sync(0xffffffffu, cnt > 0);
    int src = (mask != 0u) ? (__ffs(mask) - 1) : 0;
    col = __shfl_sync(0xffffffffu, col, src);
    val = __shfl_sync(0xffffffffu, val, src);
    if (lane == 0) {
        g_cnt[warp] = total;
        g_col[warp] = (mask != 0u) ? col : 0;
        g_val[warp] = (mask != 0u) ? val : 0.f;
    }
}

// ---------------------------------------------------------------------------
// Kernel 0b: g_maxnnz = max(g_cnt)   (single block; deterministic, no atomics
// on stale state across graph replays)
// ---------------------------------------------------------------------------
__global__ __launch_bounds__(256)
void maxnnz_kernel()
{
    const int tid = threadIdx.x;
    int m = 0;
#pragma unroll
    for (int i = tid; i < NN; i += 256) m = max(m, g_cnt[i]);
#pragma unroll
    for (int o = 16; o > 0; o >>= 1)
        m = max(m, __shfl_xor_sync(0xffffffffu, m, o));
    __shared__ int ws[8];
    if ((tid & 31) == 0) ws[tid >> 5] = m;
    __syncthreads();
    if (tid < 8) {
        int x = ws[tid];
#pragma unroll
        for (int o = 4; o > 0; o >>= 1)
            x = max(x, __shfl_xor_sync(0xffu, x, o));
        if (tid == 0) g_maxnnz = x;
    }
}

// ---------------------------------------------------------------------------
// Kernel 1 (dense fallback): C = A * B^T. Early-exits when W1 is 1-sparse.
// ---------------------------------------------------------------------------
__global__ __launch_bounds__(256, 2)
void gemm_nt_kernel(const float* __restrict__ A, const float* __restrict__ B,
                    int M, int N, int K)
{
    if (g_maxnnz <= 1) return;   // sparse fast path active -> dead launch

    constexpr int TM = 128, TN = 128, TK = 16;
    __shared__ float As[2][TK][TM + 4];
    __shared__ float Bs[2][TK][TN + 4];

    const int tid = threadIdx.x;
    const int bm = blockIdx.y * TM;
    const int bn = blockIdx.x * TN;

    const int lr = tid >> 2;
    const int lk = (tid & 3) * 4;

    const float* Ag = A + (size_t)(bm + lr) * K + lk;
    const float* Bg = B + (size_t)(bn + lr) * K + lk;

    const int tm = (tid >> 4) * 8;
    const int tn = (tid & 15) * 8;

    unsigned long long acc[8][4];
#pragma unroll
    for (int i = 0; i < 8; i++)
#pragma unroll
        for (int j = 0; j < 4; j++) acc[i][j] = 0ull;

    {
        float4 a0 = *(const float4*)(Ag);
        float4 a1 = *(const float4*)(Ag + (size_t)64 * K);
        float4 b0 = *(const float4*)(Bg);
        float4 b1 = *(const float4*)(Bg + (size_t)64 * K);
        As[0][lk + 0][lr]      = a0.x; As[0][lk + 1][lr]      = a0.y;
        As[0][lk + 2][lr]      = a0.z; As[0][lk + 3][lr]      = a0.w;
        As[0][lk + 0][lr + 64] = a1.x; As[0][lk + 1][lr + 64] = a1.y;
        As[0][lk + 2][lr + 64] = a1.z; As[0][lk + 3][lr + 64] = a1.w;
        Bs[0][lk + 0][lr]      = b0.x; Bs[0][lk + 1][lr]      = b0.y;
        Bs[0][lk + 2][lr]      = b0.z; Bs[0][lk + 3][lr]      = b0.w;
        Bs[0][lk + 0][lr + 64] = b1.x; Bs[0][lk + 1][lr + 64] = b1.y;
        Bs[0][lk + 2][lr + 64] = b1.z; Bs[0][lk + 3][lr + 64] = b1.w;
    }
    __syncthreads();

    int buf = 0;
#pragma unroll 1
    for (int kt = TK; kt <= K; kt += TK) {
        const bool last = (kt == K);
        float4 na0, na1, nb0, nb1;
        if (!last) {
            na0 = *(const float4*)(Ag + kt);
            na1 = *(const float4*)(Ag + (size_t)64 * K + kt);
            nb0 = *(const float4*)(Bg + kt);
            nb1 = *(const float4*)(Bg + (size_t)64 * K + kt);
        }

#pragma unroll
        for (int k = 0; k < TK; k++) {
            float4 af0 = *(const float4*)&As[buf][k][tm];
            float4 af1 = *(const float4*)&As[buf][k][tm + 4];
            ulonglong2 bq0 = *(const ulonglong2*)&Bs[buf][k][tn];
            ulonglong2 bq1 = *(const ulonglong2*)&Bs[buf][k][tn + 4];
            unsigned long long br[4] = {bq0.x, bq0.y, bq1.x, bq1.y};
            float ar[8] = {af0.x, af0.y, af0.z, af0.w,
                           af1.x, af1.y, af1.z, af1.w};
#pragma unroll
            for (int i = 0; i < 8; i++) {
                const unsigned long long ad = pack_dup(ar[i]);
#pragma unroll
                for (int j = 0; j < 4; j++)
                    ffma2(acc[i][j], ad, br[j]);
            }
        }

        if (!last) {
            const int nb = buf ^ 1;
            As[nb][lk + 0][lr]      = na0.x; As[nb][lk + 1][lr]      = na0.y;
            As[nb][lk + 2][lr]      = na0.z; As[nb][lk + 3][lr]      = na0.w;
            As[nb][lk + 0][lr + 64] = na1.x; As[nb][lk + 1][lr + 64] = na1.y;
            As[nb][lk + 2][lr + 64] = na1.z; As[nb][lk + 3][lr + 64] = na1.w;
            Bs[nb][lk + 0][lr]      = nb0.x; Bs[nb][lk + 1][lr]      = nb0.y;
            Bs[nb][lk + 2][lr]      = nb0.z; Bs[nb][lk + 3][lr]      = nb0.w;
            Bs[nb][lk + 0][lr + 64] = nb1.x; Bs[nb][lk + 1][lr + 64] = nb1.y;
            Bs[nb][lk + 2][lr + 64] = nb1.z; Bs[nb][lk + 3][lr + 64] = nb1.w;
            __syncthreads();
            buf = nb;
        }
    }

#pragma unroll
    for (int i = 0; i < 8; i++) {
        float* Cr = g_I + (size_t)(bm + tm + i) * N + bn + tn;
        ulonglong2 w0; w0.x = acc[i][0]; w0.y = acc[i][1];
        ulonglong2 w1; w1.x = acc[i][2]; w1.y = acc[i][3];
        *(ulonglong2*)(Cr)     = w0;
        *(ulonglong2*)(Cr + 4) = w1;
    }
}

// ---------------------------------------------------------------------------
// Izhikevich Euler step (same association as the passing R3/R4 kernel)
// ---------------------------------------------------------------------------
__device__ __forceinline__ void izh_step(float In, float dtn, float dta,
                                         float bn, float cn, float dn, float thn,
                                         float& v, float& u, float& s)
{
    const float poly = 0.04f * v * v + 5.0f * v + 140.0f - u + In;
    const float vn = v + dtn * poly;
    const float un = u + dta * (bn * v - u);
    const bool  f  = (vn > thn);
    s = f ? 1.0f : 0.0f;
    v = f ? cn : vn;
    u = fmaf(dn, s, un);   // un + d*s, exact for s in {0,1}
}

// ---------------------------------------------------------------------------
// Kernel 2: per-neuron serial scan. ONE neuron per thread, 32 warps spread
// over 32 blocks (one warp each) -> min issue pressure per SMSP.
// Sparse path gathers I = val * X[t, col] directly; dense path reads g_I.
// ---------------------------------------------------------------------------
__global__ __launch_bounds__(32)
void scan_kernel(const float* __restrict__ X,
                 const float* __restrict__ st0,
                 const float* __restrict__ a_, const float* __restrict__ b_,
                 const float* __restrict__ c_, const float* __restrict__ d_,
                 const float* __restrict__ th_, const float* __restrict__ dt_,
                 float* __restrict__ spikes, float* __restrict__ states)
{
    const int n = blockIdx.x * 32 + threadIdx.x;   // 0..1023

    float v = st0[n];
    float u = st0[NN + n];
    const float an  = a_[n],  bn  = b_[n];
    const float cn  = c_[n],  dn  = d_[n];
    const float thn = th_[n], dtn = dt_[n];
    const float dta = dtn * an;

    float* sp = spikes + n;          // stride NN
    float* vp = states + n;          // stride 2*NN
    float* up = states + NN + n;

    constexpr int PF = 8;
    float pf[PF];
    float s;

    if (g_maxnnz <= 1) {
        // ---- sparse fast path: I[t,n] = val * X[t, col] (bit-identical to GEMM) ----
        const int   col = g_col[n];
        const float w   = g_val[n];
        const float* Xc = X + col;   // stride NN

#pragma unroll
        for (int i = 0; i < PF; i++) pf[i] = w * Xc[(size_t)i * NN];

#pragma unroll 1
        for (int t0 = 0; t0 < TSTEPS - PF; t0 += PF) {
#pragma unroll
            for (int k = 0; k < PF; k++) {
                const int t = t0 + k;
                const float In = pf[k];
                pf[k] = w * Xc[(size_t)(t + PF) * NN];
                izh_step(In, dtn, dta, bn, cn, dn, thn, v, u, s);
                sp[(size_t)t * NN]     = s;
                vp[(size_t)t * 2 * NN] = v;
                up[(size_t)t * 2 * NN] = u;
            }
        }
#pragma unroll
        for (int k = 0; k < PF; k++) {
            const int t = TSTEPS - PF + k;
            izh_step(pf[k], dtn, dta, bn, cn, dn, thn, v, u, s);
            sp[(size_t)t * NN]     = s;
            vp[(size_t)t * 2 * NN] = v;
            up[(size_t)t * 2 * NN] = u;
        }
    } else {
        // ---- dense fallback: read precomputed g_I ----
        const float* Ip = g_I + n;   // stride NN

#pragma unroll
        for (int i = 0; i < PF; i++) pf[i] = Ip[(size_t)i * NN];

#pragma unroll 1
        for (int t0 = 0; t0 < TSTEPS - PF; t0 += PF) {
#pragma unroll
            for (int k = 0; k < PF; k++) {
                const int t = t0 + k;
                const float In = pf[k];
                pf[k] = Ip[(size_t)(t + PF) * NN];
                izh_step(In, dtn, dta, bn, cn, dn, thn, v, u, s);
                sp[(size_t)t * NN]     = s;
                vp[(size_t)t * 2 * NN] = v;
                up[(size_t)t * 2 * NN] = u;
            }
        }
#pragma unroll
        for (int k = 0; k < PF; k++) {
            const int t = TSTEPS - PF + k;
            izh_step(pf[k], dtn, dta, bn, cn, dn, thn, v, u, s);
            sp[(size_t)t * NN]     = s;
            vp[(size_t)t * 2 * NN] = v;
            up[(size_t)t * 2 * NN] = u;
        }
    }
}

// ---------------------------------------------------------------------------
// Kernel 3: S[t] = sum_n W2[n] * spikes[t,n]   (one block per timestep)
// ---------------------------------------------------------------------------
__global__ __launch_bounds__(256)
void rowsum_kernel(const float* __restrict__ spikes, const float* __restrict__ w2)
{
    const int t = blockIdx.x;
    const int tid = threadIdx.x;
    const float4 sv = ((const float4*)(spikes + (size_t)t * NN))[tid];
    const float4 wv = ((const float4*)w2)[tid];
    float sum = sv.x * wv.x + sv.y * wv.y + sv.z * wv.z + sv.w * wv.w;

#pragma unroll
    for (int o = 16; o > 0; o >>= 1)
        sum += __shfl_xor_sync(0xffffffffu, sum, o);

    __shared__ float ws[8];
    if ((tid & 31) == 0) ws[tid >> 5] = sum;
    __syncthreads();
    if (tid < 8) {
        float x = ws[tid];
#pragma unroll
        for (int o = 4; o > 0; o >>= 1)
            x += __shfl_xor_sync(0xffu, x, o);
        if (tid == 0) g_S[t] = x;
    }
}

// ---------------------------------------------------------------------------
// Kernel 4: parallel decode scan (affine composition, Hillis-Steele)
// ---------------------------------------------------------------------------
__global__ __launch_bounds__(1024)
void decode_scan_kernel(const float* __restrict__ leak,
                        float* __restrict__ decoded)
{
    constexpr int C = TSTEPS / 1024;   // 8
    __shared__ float s_scale[1024];
    __shared__ float s_off[1024];

    const int tid = threadIdx.x;
    const float L = leak[0];
    const int base = tid * C;

    float vals[C];
#pragma unroll
    for (int k = 0; k < C; k++) vals[k] = g_S[base + k];

    float dm = 0.f;
#pragma unroll
    for (int k = 0; k < C; k++) dm = L * dm + vals[k];
    float L2 = L * L, L4 = L2 * L2, L8 = L4 * L4;

    float myS = L8, myO = dm;
    s_scale[tid] = myS; s_off[tid] = myO;
    __syncthreads();

    for (int d = 1; d < 1024; d <<= 1) {
        float ps = 1.f, po = 0.f;
        if (tid >= d) { ps = s_scale[tid - d]; po = s_off[tid - d]; }
        __syncthreads();
        myO = myS * po + myO;
        myS = myS * ps;
        s_scale[tid] = myS; s_off[tid] = myO;
        __syncthreads();
    }

    const float carry_in = (tid == 0) ? 0.f : s_off[tid - 1];

    dm = carry_in;
#pragma unroll
    for (int k = 0; k < C; k++) {
        dm = L * dm + vals[k];
        decoded[base + k] = dm;
    }
}

// ---------------------------------------------------------------------------
extern "C" void kernel_launch(void* const* d_in, const int* in_sizes, int n_in,
                              void* d_out, int out_size)
{
    const float* X    = (const float*)d_in[0];   // [T, N]
    const float* st0  = (const float*)d_in[1];   // [2, N]
    const float* W1   = (const float*)d_in[2];   // [N, N]
    const float* W2   = (const float*)d_in[3];   // [1, N]
    const float* a    = (const float*)d_in[4];
    const float* b    = (const float*)d_in[5];
    const float* c    = (const float*)d_in[6];
    const float* d    = (const float*)d_in[7];
    const float* th   = (const float*)d_in[8];
    const float* dt   = (const float*)d_in[9];
    const float* leak = (const float*)d_in[10];

    float* out     = (float*)d_out;
    float* spikes  = out;                                       // [T, N]
    float* states  = out + (size_t)TSTEPS * NN;                 // [T, 2, N]
    float* decoded = out + (size_t)TSTEPS * NN * 3;             // [T, 1]

    // 0) W1 sparsity analysis
    analyze_kernel<<<NN / 8, 256>>>(W1);
    maxnnz_kernel<<<1, 256>>>();

    // 1) dense fallback GEMM (dead launch when W1 is <=1-sparse per row)
    dim3 ggrid(NN / 128, TSTEPS / 128);
    gemm_nt_kernel<<<ggrid, 256>>>(X, W1, TSTEPS, NN, NN);

    // 2) per-neuron scan (sparse gather or g_I)
    scan_kernel<<<NN / 32, 32>>>(X, st0, a, b, c, d, th, dt, spikes, states);

    // 3) per-step weighted spike sums
    rowsum_kernel<<<TSTEPS, 256>>>(spikes, W2);

    // 4) decode leaky integrator (parallel affine scan)
    decode_scan_kernel<<<1, 1024>>>(leak, decoded);
}

// round 11
// speedup vs baseline: 1.7961x; 1.0191x over previous
#include <cuda_runtime.h>
#include <cuda_bf16.h>
#include <cstdint>

#define TSTEPS 8192
#define NN     1024

// Scratch (device globals; no allocation allowed in kernel_launch)
__device__ float g_I[(size_t)TSTEPS * NN];   // I_all = X @ W1^T (GEMM or expand)
__device__ float g_S[TSTEPS];                // per-step weighted spike sum
__device__ int   g_cnt[NN];                  // nonzeros per W1 row
__device__ __align__(16) int   g_col[NN];    // col of the single nonzero (if nnz<=1)
__device__ __align__(16) float g_val[NN];    // val of the single nonzero
__device__ int   g_maxnnz;                   // max row nnz; <=1 -> sparse fast path

// ---------------------------------------------------------------------------
// Packed fp32x2 helpers (Blackwell FFMA2)
// ---------------------------------------------------------------------------
__device__ __forceinline__ unsigned long long pack_dup(float x) {
    unsigned long long r;
    asm("mov.b64 %0, {%1, %1};" : "=l"(r) : "f"(x));
    return r;
}
__device__ __forceinline__ void ffma2(unsigned long long& d,
                                      unsigned long long a,
                                      unsigned long long b) {
    asm("fma.rn.f32x2 %0, %1, %2, %0;" : "+l"(d) : "l"(a), "l"(b));
}

// ---------------------------------------------------------------------------
// Kernel 0a: analyze W1 sparsity. One warp per row.
// ---------------------------------------------------------------------------
__global__ __launch_bounds__(256)
void analyze_kernel(const float* __restrict__ W1)
{
    const int warp = (blockIdx.x * blockDim.x + threadIdx.x) >> 5;
    const int lane = threadIdx.x & 31;
    if (warp >= NN) return;
    const float* row = W1 + (size_t)warp * NN;

    int   cnt = 0, col = 0;
    float val = 0.f;
#pragma unroll 4
    for (int c = lane; c < NN; c += 32) {
        float w = row[c];
        if (w != 0.f) { cnt++; col = c; val = w; }
    }
    int total = cnt;
#pragma unroll
    for (int o = 16; o > 0; o >>= 1)
        total += __shfl_xor_sync(0xffffffffu, total, o);
    unsigned mask = __ballot_sync(0xffffffffu, cnt > 0);
    int src = (mask != 0u) ? (__ffs(mask) - 1) : 0;
    col = __shfl_sync(0xffffffffu, col, src);
    val = __shfl_sync(0xffffffffu, val, src);
    if (lane == 0) {
        g_cnt[warp] = total;
        g_col[warp] = (mask != 0u) ? col : 0;
        g_val[warp] = (mask != 0u) ? val : 0.f;
    }
}

// ---------------------------------------------------------------------------
// Kernel 0b: g_maxnnz = max(g_cnt)
// ---------------------------------------------------------------------------
__global__ __launch_bounds__(256)
void maxnnz_kernel()
{
    const int tid = threadIdx.x;
    int m = 0;
#pragma unroll
    for (int i = tid; i < NN; i += 256) m = max(m, g_cnt[i]);
#pragma unroll
    for (int o = 16; o > 0; o >>= 1)
        m = max(m, __shfl_xor_sync(0xffffffffu, m, o));
    __shared__ int ws[8];
    if ((tid & 31) == 0) ws[tid >> 5] = m;
    __syncthreads();
    if (tid < 8) {
        int x = ws[tid];
#pragma unroll
        for (int o = 4; o > 0; o >>= 1)
            x = max(x, __shfl_xor_sync(0xffu, x, o));
        if (tid == 0) g_maxnnz = x;
    }
}

// ---------------------------------------------------------------------------
// Kernel 1 (dense fallback): C = A * B^T. Early-exits when W1 is 1-sparse.
// ---------------------------------------------------------------------------
__global__ __launch_bounds__(256, 2)
void gemm_nt_kernel(const float* __restrict__ A, const float* __restrict__ B,
                    int M, int N, int K)
{
    if (g_maxnnz <= 1) return;   // sparse fast path active -> dead launch

    constexpr int TM = 128, TN = 128, TK = 16;
    __shared__ float As[2][TK][TM + 4];
    __shared__ float Bs[2][TK][TN + 4];

    const int tid = threadIdx.x;
    const int bm = blockIdx.y * TM;
    const int bn = blockIdx.x * TN;

    const int lr = tid >> 2;
    const int lk = (tid & 3) * 4;

    const float* Ag = A + (size_t)(bm + lr) * K + lk;
    const float* Bg = B + (size_t)(bn + lr) * K + lk;

    const int tm = (tid >> 4) * 8;
    const int tn = (tid & 15) * 8;

    unsigned long long acc[8][4];
#pragma unroll
    for (int i = 0; i < 8; i++)
#pragma unroll
        for (int j = 0; j < 4; j++) acc[i][j] = 0ull;

    {
        float4 a0 = *(const float4*)(Ag);
        float4 a1 = *(const float4*)(Ag + (size_t)64 * K);
        float4 b0 = *(const float4*)(Bg);
        float4 b1 = *(const float4*)(Bg + (size_t)64 * K);
        As[0][lk + 0][lr]      = a0.x; As[0][lk + 1][lr]      = a0.y;
        As[0][lk + 2][lr]      = a0.z; As[0][lk + 3][lr]      = a0.w;
        As[0][lk + 0][lr + 64] = a1.x; As[0][lk + 1][lr + 64] = a1.y;
        As[0][lk + 2][lr + 64] = a1.z; As[0][lk + 3][lr + 64] = a1.w;
        Bs[0][lk + 0][lr]      = b0.x; Bs[0][lk + 1][lr]      = b0.y;
        Bs[0][lk + 2][lr]      = b0.z; Bs[0][lk + 3][lr]      = b0.w;
        Bs[0][lk + 0][lr + 64] = b1.x; Bs[0][lk + 1][lr + 64] = b1.y;
        Bs[0][lk + 2][lr + 64] = b1.z; Bs[0][lk + 3][lr + 64] = b1.w;
    }
    __syncthreads();

    int buf = 0;
#pragma unroll 1
    for (int kt = TK; kt <= K; kt += TK) {
        const bool last = (kt == K);
        float4 na0, na1, nb0, nb1;
        if (!last) {
            na0 = *(const float4*)(Ag + kt);
            na1 = *(const float4*)(Ag + (size_t)64 * K + kt);
            nb0 = *(const float4*)(Bg + kt);
            nb1 = *(const float4*)(Bg + (size_t)64 * K + kt);
        }

#pragma unroll
        for (int k = 0; k < TK; k++) {
            float4 af0 = *(const float4*)&As[buf][k][tm];
            float4 af1 = *(const float4*)&As[buf][k][tm + 4];
            ulonglong2 bq0 = *(const ulonglong2*)&Bs[buf][k][tn];
            ulonglong2 bq1 = *(const ulonglong2*)&Bs[buf][k][tn + 4];
            unsigned long long br[4] = {bq0.x, bq0.y, bq1.x, bq1.y};
            float ar[8] = {af0.x, af0.y, af0.z, af0.w,
                           af1.x, af1.y, af1.z, af1.w};
#pragma unroll
            for (int i = 0; i < 8; i++) {
                const unsigned long long ad = pack_dup(ar[i]);
#pragma unroll
                for (int j = 0; j < 4; j++)
                    ffma2(acc[i][j], ad, br[j]);
            }
        }

        if (!last) {
            const int nb = buf ^ 1;
            As[nb][lk + 0][lr]      = na0.x; As[nb][lk + 1][lr]      = na0.y;
            As[nb][lk + 2][lr]      = na0.z; As[nb][lk + 3][lr]      = na0.w;
            As[nb][lk + 0][lr + 64] = na1.x; As[nb][lk + 1][lr + 64] = na1.y;
            As[nb][lk + 2][lr + 64] = na1.z; As[nb][lk + 3][lr + 64] = na1.w;
            Bs[nb][lk + 0][lr]      = nb0.x; Bs[nb][lk + 1][lr]      = nb0.y;
            Bs[nb][lk + 2][lr]      = nb0.z; Bs[nb][lk + 3][lr]      = nb0.w;
            Bs[nb][lk + 0][lr + 64] = nb1.x; Bs[nb][lk + 1][lr + 64] = nb1.y;
            Bs[nb][lk + 2][lr + 64] = nb1.z; Bs[nb][lk + 3][lr + 64] = nb1.w;
            __syncthreads();
            buf = nb;
        }
    }

#pragma unroll
    for (int i = 0; i < 8; i++) {
        float* Cr = g_I + (size_t)(bm + tm + i) * N + bn + tn;
        ulonglong2 w0; w0.x = acc[i][0]; w0.y = acc[i][1];
        ulonglong2 w1; w1.x = acc[i][2]; w1.y = acc[i][3];
        *(ulonglong2*)(Cr)     = w0;
        *(ulonglong2*)(Cr + 4) = w1;
    }
}

// ---------------------------------------------------------------------------
// Kernel 1b (sparse path): g_I[t,n] = val[n] * X[t, col[n]].
// __fmul_rn = one explicit rounding, bit-identical to the GEMM's
// fma(x, w, 0) single-nonzero sum. Mul feeds a store -> cannot be
// FMA-contracted into anything (the R8/R10 failure mechanism).
// ---------------------------------------------------------------------------
__global__ __launch_bounds__(256)
void expand_kernel(const float* __restrict__ X)
{
    if (g_maxnnz > 1) return;    // dense fallback active -> dead launch
    const int t  = blockIdx.x;
    const int n0 = threadIdx.x * 4;
    const float* Xr = X + (size_t)t * NN;
    const int4   c = *(const int4*)(g_col + n0);
    const float4 w = *(const float4*)(g_val + n0);
    float4 o;
    o.x = __fmul_rn(w.x, Xr[c.x]);
    o.y = __fmul_rn(w.y, Xr[c.y]);
    o.z = __fmul_rn(w.z, Xr[c.z]);
    o.w = __fmul_rn(w.w, Xr[c.w]);
    *(float4*)(g_I + (size_t)t * NN + n0) = o;
}

// ---------------------------------------------------------------------------
// Izhikevich Euler step — verbatim numerics of the R4 passing kernel.
// In must ALWAYS arrive as a pre-rounded value (load or earlier-rounded reg);
// never pass a fresh multiply (FMA contraction flips spikes — R8/R10).
// ---------------------------------------------------------------------------
__device__ __forceinline__ void izh_step(float In, float dtn, float dta,
                                         float bn, float cn, float dn, float thn,
                                         float& v, float& u, float& s)
{
    const float poly = 0.04f * v * v + 5.0f * v + 140.0f - u + In;
    const float vn = v + dtn * poly;
    const float un = u + dta * (bn * v - u);
    const bool  f  = (vn > thn);
    s = f ? 1.0f : 0.0f;
    v = f ? cn : vn;
    u = fmaf(dn, s, un);   // un + d*s, exact for s in {0,1}
}

// ---------------------------------------------------------------------------
// Kernel 2: per-neuron serial scan. TWO neurons per thread (adjacent n ->
// float2 I/O), 512 threads as 16 one-warp blocks (one warp per SM).
// Always reads g_I (proven R3 data path); no weight multiply anywhere.
// ---------------------------------------------------------------------------
__global__ __launch_bounds__(32)
void scan_kernel(const float* __restrict__ st0,
                 const float* __restrict__ a_, const float* __restrict__ b_,
                 const float* __restrict__ c_, const float* __restrict__ d_,
                 const float* __restrict__ th_, const float* __restrict__ dt_,
                 float* __restrict__ spikes, float* __restrict__ states)
{
    const int p = blockIdx.x * 32 + threadIdx.x;   // 0..511
    const int n = 2 * p;

    float v0 = st0[n],      v1 = st0[n + 1];
    float u0 = st0[NN + n], u1 = st0[NN + n + 1];
    const float2 aa = *(const float2*)(a_  + n);
    const float2 bb = *(const float2*)(b_  + n);
    const float2 cc = *(const float2*)(c_  + n);
    const float2 dd = *(const float2*)(d_  + n);
    const float2 th = *(const float2*)(th_ + n);
    const float2 dt = *(const float2*)(dt_ + n);
    const float dta0 = dt.x * aa.x;
    const float dta1 = dt.y * aa.y;

    const float2* Ip = (const float2*)g_I + p;      // row stride NN/2
    float2* sp = (float2*)spikes + p;               // row stride NN/2
    float2* vp = (float2*)states + p;               // row stride NN
    float2* up = (float2*)states + (NN / 2) + p;

    constexpr int PF = 8;
    float2 pf[PF];
    float s0, s1;

#pragma unroll
    for (int i = 0; i < PF; i++) pf[i] = Ip[(size_t)i * (NN / 2)];

#pragma unroll 1
    for (int t0 = 0; t0 < TSTEPS - PF; t0 += PF) {
#pragma unroll
        for (int k = 0; k < PF; k++) {
            const int t = t0 + k;
            const float2 In = pf[k];
            pf[k] = Ip[(size_t)(t + PF) * (NN / 2)];   // raw prefetch, no consumer

            izh_step(In.x, dt.x, dta0, bb.x, cc.x, dd.x, th.x, v0, u0, s0);
            izh_step(In.y, dt.y, dta1, bb.y, cc.y, dd.y, th.y, v1, u1, s1);

            sp[(size_t)t * (NN / 2)] = make_float2(s0, s1);
            vp[(size_t)t * NN]       = make_float2(v0, v1);
            up[(size_t)t * NN]       = make_float2(u0, u1);
        }
    }
#pragma unroll
    for (int k = 0; k < PF; k++) {
        const int t = TSTEPS - PF + k;
        const float2 In = pf[k];
        izh_step(In.x, dt.x, dta0, bb.x, cc.x, dd.x, th.x, v0, u0, s0);
        izh_step(In.y, dt.y, dta1, bb.y, cc.y, dd.y, th.y, v1, u1, s1);
        sp[(size_t)t * (NN / 2)] = make_float2(s0, s1);
        vp[(size_t)t * NN]       = make_float2(v0, v1);
        up[(size_t)t * NN]       = make_float2(u0, u1);
    }
}

// ---------------------------------------------------------------------------
// Kernel 3: S[t] = sum_n W2[n] * spikes[t,n]   (one block per timestep)
// ---------------------------------------------------------------------------
__global__ __launch_bounds__(256)
void rowsum_kernel(const float* __restrict__ spikes, const float* __restrict__ w2)
{
    const int t = blockIdx.x;
    const int tid = threadIdx.x;
    const float4 sv = ((const float4*)(spikes + (size_t)t * NN))[tid];
    const float4 wv = ((const float4*)w2)[tid];
    float sum = sv.x * wv.x + sv.y * wv.y + sv.z * wv.z + sv.w * wv.w;

#pragma unroll
    for (int o = 16; o > 0; o >>= 1)
        sum += __shfl_xor_sync(0xffffffffu, sum, o);

    __shared__ float ws[8];
    if ((tid & 31) == 0) ws[tid >> 5] = sum;
    __syncthreads();
    if (tid < 8) {
        float x = ws[tid];
#pragma unroll
        for (int o = 4; o > 0; o >>= 1)
            x += __shfl_xor_sync(0xffu, x, o);
        if (tid == 0) g_S[t] = x;
    }
}

// ---------------------------------------------------------------------------
// Kernel 4: parallel decode scan (affine composition, Hillis-Steele)
// ---------------------------------------------------------------------------
__global__ __launch_bounds__(1024)
void decode_scan_kernel(const float* __restrict__ leak,
                        float* __restrict__ decoded)
{
    constexpr int C = TSTEPS / 1024;   // 8
    __shared__ float s_scale[1024];
    __shared__ float s_off[1024];

    const int tid = threadIdx.x;
    const float L = leak[0];
    const int base = tid * C;

    float vals[C];
#pragma unroll
    for (int k = 0; k < C; k++) vals[k] = g_S[base + k];

    float dm = 0.f;
#pragma unroll
    for (int k = 0; k < C; k++) dm = L * dm + vals[k];
    float L2 = L * L, L4 = L2 * L2, L8 = L4 * L4;

    float myS = L8, myO = dm;
    s_scale[tid] = myS; s_off[tid] = myO;
    __syncthreads();

    for (int d = 1; d < 1024; d <<= 1) {
        float ps = 1.f, po = 0.f;
        if (tid >= d) { ps = s_scale[tid - d]; po = s_off[tid - d]; }
        __syncthreads();
        myO = myS * po + myO;
        myS = myS * ps;
        s_scale[tid] = myS; s_off[tid] = myO;
        __syncthreads();
    }

    const float carry_in = (tid == 0) ? 0.f : s_off[tid - 1];

    dm = carry_in;
#pragma unroll
    for (int k = 0; k < C; k++) {
        dm = L * dm + vals[k];
        decoded[base + k] = dm;
    }
}

// ---------------------------------------------------------------------------
extern "C" void kernel_launch(void* const* d_in, const int* in_sizes, int n_in,
                              void* d_out, int out_size)
{
    const float* X    = (const float*)d_in[0];   // [T, N]
    const float* st0  = (const float*)d_in[1];   // [2, N]
    const float* W1   = (const float*)d_in[2];   // [N, N]
    const float* W2   = (const float*)d_in[3];   // [1, N]
    const float* a    = (const float*)d_in[4];
    const float* b    = (const float*)d_in[5];
    const float* c    = (const float*)d_in[6];
    const float* d    = (const float*)d_in[7];
    const float* th   = (const float*)d_in[8];
    const float* dt   = (const float*)d_in[9];
    const float* leak = (const float*)d_in[10];

    float* out     = (float*)d_out;
    float* spikes  = out;                                       // [T, N]
    float* states  = out + (size_t)TSTEPS * NN;                 // [T, 2, N]
    float* decoded = out + (size_t)TSTEPS * NN * 3;             // [T, 1]

    // 0) W1 sparsity analysis
    analyze_kernel<<<NN / 8, 256>>>(W1);
    maxnnz_kernel<<<1, 256>>>();

    // 1) fill g_I: dense GEMM (dead when sparse) / sparse expand (dead when dense)
    dim3 ggrid(NN / 128, TSTEPS / 128);
    gemm_nt_kernel<<<ggrid, 256>>>(X, W1, TSTEPS, NN, NN);
    expand_kernel<<<TSTEPS, 256>>>(X);

    // 2) per-neuron scan: 2 neurons/thread, raw g_I prefetch (proven path)
    scan_kernel<<<16, 32>>>(st0, a, b, c, d, th, dt, spikes, states);

    // 3) per-step weighted spike sums
    rowsum_kernel<<<TSTEPS, 256>>>(spikes, W2);

    // 4) decode leaky integrator (parallel affine scan)
    decode_scan_kernel<<<1, 1024>>>(leak, decoded);
}

// round 12
// speedup vs baseline: 3.3428x; 1.8612x over previous
#include <cuda_runtime.h>
#include <cuda_bf16.h>
#include <cstdint>

#define TSTEPS 8192
#define NN     1024

// Scratch (device globals; no allocation allowed in kernel_launch)
__device__ float g_I[(size_t)TSTEPS * NN];   // I_all = X @ W1^T (GEMM or expand)
__device__ float g_S[TSTEPS];                // per-step weighted spike sum
__device__ int   g_cnt[NN];                  // nonzeros per W1 row
__device__ __align__(16) int   g_col[NN];    // col of the single nonzero (if nnz<=1)
__device__ __align__(16) float g_val[NN];    // val of the single nonzero
__device__ int   g_maxnnz;                   // max row nnz; <=1 -> sparse fast path

// ---------------------------------------------------------------------------
// Packed fp32x2 helpers (Blackwell FFMA2)
// ---------------------------------------------------------------------------
__device__ __forceinline__ unsigned long long pack_dup(float x) {
    unsigned long long r;
    asm("mov.b64 %0, {%1, %1};" : "=l"(r) : "f"(x));
    return r;
}
__device__ __forceinline__ void ffma2(unsigned long long& d,
                                      unsigned long long a,
                                      unsigned long long b) {
    asm("fma.rn.f32x2 %0, %1, %2, %0;" : "+l"(d) : "l"(a), "l"(b));
}

// ---------------------------------------------------------------------------
// Kernel 0a: analyze W1 sparsity. One warp per row.
// ---------------------------------------------------------------------------
__global__ __launch_bounds__(256)
void analyze_kernel(const float* __restrict__ W1)
{
    const int warp = (blockIdx.x * blockDim.x + threadIdx.x) >> 5;
    const int lane = threadIdx.x & 31;
    if (warp >= NN) return;
    const float* row = W1 + (size_t)warp * NN;

    int   cnt = 0, col = 0;
    float val = 0.f;
#pragma unroll 4
    for (int c = lane; c < NN; c += 32) {
        float w = row[c];
        if (w != 0.f) { cnt++; col = c; val = w; }
    }
    int total = cnt;
#pragma unroll
    for (int o = 16; o > 0; o >>= 1)
        total += __shfl_xor_sync(0xffffffffu, total, o);
    unsigned mask = __ballot_sync(0xffffffffu, cnt > 0);
    int src = (mask != 0u) ? (__ffs(mask) - 1) : 0;
    col = __shfl_sync(0xffffffffu, col, src);
    val = __shfl_sync(0xffffffffu, val, src);
    if (lane == 0) {
        g_cnt[warp] = total;
        g_col[warp] = (mask != 0u) ? col : 0;
        g_val[warp] = (mask != 0u) ? val : 0.f;
    }
}

// ---------------------------------------------------------------------------
// Kernel 0b: g_maxnnz = max(g_cnt)
// ---------------------------------------------------------------------------
__global__ __launch_bounds__(256)
void maxnnz_kernel()
{
    const int tid = threadIdx.x;
    int m = 0;
#pragma unroll
    for (int i = tid; i < NN; i += 256) m = max(m, g_cnt[i]);
#pragma unroll
    for (int o = 16; o > 0; o >>= 1)
        m = max(m, __shfl_xor_sync(0xffffffffu, m, o));
    __shared__ int ws[8];
    if ((tid & 31) == 0) ws[tid >> 5] = m;
    __syncthreads();
    if (tid < 8) {
        int x = ws[tid];
#pragma unroll
        for (int o = 4; o > 0; o >>= 1)
            x = max(x, __shfl_xor_sync(0xffu, x, o));
        if (tid == 0) g_maxnnz = x;
    }
}

// ---------------------------------------------------------------------------
// Kernel 1 (dense fallback): C = A * B^T. Early-exits when W1 is 1-sparse.
// ---------------------------------------------------------------------------
__global__ __launch_bounds__(256, 2)
void gemm_nt_kernel(const float* __restrict__ A, const float* __restrict__ B,
                    int M, int N, int K)
{
    if (g_maxnnz <= 1) return;   // sparse fast path active -> dead launch

    constexpr int TM = 128, TN = 128, TK = 16;
    __shared__ float As[2][TK][TM + 4];
    __shared__ float Bs[2][TK][TN + 4];

    const int tid = threadIdx.x;
    const int bm = blockIdx.y * TM;
    const int bn = blockIdx.x * TN;

    const int lr = tid >> 2;
    const int lk = (tid & 3) * 4;

    const float* Ag = A + (size_t)(bm + lr) * K + lk;
    const float* Bg = B + (size_t)(bn + lr) * K + lk;

    const int tm = (tid >> 4) * 8;
    const int tn = (tid & 15) * 8;

    unsigned long long acc[8][4];
#pragma unroll
    for (int i = 0; i < 8; i++)
#pragma unroll
        for (int j = 0; j < 4; j++) acc[i][j] = 0ull;

    {
        float4 a0 = *(const float4*)(Ag);
        float4 a1 = *(const float4*)(Ag + (size_t)64 * K);
        float4 b0 = *(const float4*)(Bg);
        float4 b1 = *(const float4*)(Bg + (size_t)64 * K);
        As[0][lk + 0][lr]      = a0.x; As[0][lk + 1][lr]      = a0.y;
        As[0][lk + 2][lr]      = a0.z; As[0][lk + 3][lr]      = a0.w;
        As[0][lk + 0][lr + 64] = a1.x; As[0][lk + 1][lr + 64] = a1.y;
        As[0][lk + 2][lr + 64] = a1.z; As[0][lk + 3][lr + 64] = a1.w;
        Bs[0][lk + 0][lr]      = b0.x; Bs[0][lk + 1][lr]      = b0.y;
        Bs[0][lk + 2][lr]      = b0.z; Bs[0][lk + 3][lr]      = b0.w;
        Bs[0][lk + 0][lr + 64] = b1.x; Bs[0][lk + 1][lr + 64] = b1.y;
        Bs[0][lk + 2][lr + 64] = b1.z; Bs[0][lk + 3][lr + 64] = b1.w;
    }
    __syncthreads();

    int buf = 0;
#pragma unroll 1
    for (int kt = TK; kt <= K; kt += TK) {
        const bool last = (kt == K);
        float4 na0, na1, nb0, nb1;
        if (!last) {
            na0 = *(const float4*)(Ag + kt);
            na1 = *(const float4*)(Ag + (size_t)64 * K + kt);
            nb0 = *(const float4*)(Bg + kt);
            nb1 = *(const float4*)(Bg + (size_t)64 * K + kt);
        }

#pragma unroll
        for (int k = 0; k < TK; k++) {
            float4 af0 = *(const float4*)&As[buf][k][tm];
            float4 af1 = *(const float4*)&As[buf][k][tm + 4];
            ulonglong2 bq0 = *(const ulonglong2*)&Bs[buf][k][tn];
            ulonglong2 bq1 = *(const ulonglong2*)&Bs[buf][k][tn + 4];
            unsigned long long br[4] = {bq0.x, bq0.y, bq1.x, bq1.y};
            float ar[8] = {af0.x, af0.y, af0.z, af0.w,
                           af1.x, af1.y, af1.z, af1.w};
#pragma unroll
            for (int i = 0; i < 8; i++) {
                const unsigned long long ad = pack_dup(ar[i]);
#pragma unroll
                for (int j = 0; j < 4; j++)
                    ffma2(acc[i][j], ad, br[j]);
            }
        }

        if (!last) {
            const int nb = buf ^ 1;
            As[nb][lk + 0][lr]      = na0.x; As[nb][lk + 1][lr]      = na0.y;
            As[nb][lk + 2][lr]      = na0.z; As[nb][lk + 3][lr]      = na0.w;
            As[nb][lk + 0][lr + 64] = na1.x; As[nb][lk + 1][lr + 64] = na1.y;
            As[nb][lk + 2][lr + 64] = na1.z; As[nb][lk + 3][lr + 64] = na1.w;
            Bs[nb][lk + 0][lr]      = nb0.x; Bs[nb][lk + 1][lr]      = nb0.y;
            Bs[nb][lk + 2][lr]      = nb0.z; Bs[nb][lk + 3][lr]      = nb0.w;
            Bs[nb][lk + 0][lr + 64] = nb1.x; Bs[nb][lk + 1][lr + 64] = nb1.y;
            Bs[nb][lk + 2][lr + 64] = nb1.z; Bs[nb][lk + 3][lr + 64] = nb1.w;
            __syncthreads();
            buf = nb;
        }
    }

#pragma unroll
    for (int i = 0; i < 8; i++) {
        float* Cr = g_I + (size_t)(bm + tm + i) * N + bn + tn;
        ulonglong2 w0; w0.x = acc[i][0]; w0.y = acc[i][1];
        ulonglong2 w1; w1.x = acc[i][2]; w1.y = acc[i][3];
        *(ulonglong2*)(Cr)     = w0;
        *(ulonglong2*)(Cr + 4) = w1;
    }
}

// ---------------------------------------------------------------------------
// Kernel 1b (sparse path): g_I[t,n] = val[n] * X[t, col[n]].
// __fmul_rn = one explicit rounding, bit-identical to the GEMM's
// fma(x, w, 0) single-nonzero sum; cannot be FMA-contracted.
// ---------------------------------------------------------------------------
__global__ __launch_bounds__(256)
void expand_kernel(const float* __restrict__ X)
{
    if (g_maxnnz > 1) return;    // dense fallback active -> dead launch
    const int t  = blockIdx.x;
    const int n0 = threadIdx.x * 4;
    const float* Xr = X + (size_t)t * NN;
    const int4   c = *(const int4*)(g_col + n0);
    const float4 w = *(const float4*)(g_val + n0);
    float4 o;
    o.x = __fmul_rn(w.x, Xr[c.x]);
    o.y = __fmul_rn(w.y, Xr[c.y]);
    o.z = __fmul_rn(w.z, Xr[c.z]);
    o.w = __fmul_rn(w.w, Xr[c.w]);
    *(float4*)(g_I + (size_t)t * NN + n0) = o;
}

// ---------------------------------------------------------------------------
// Izhikevich Euler step — verbatim numerics of the R4/R11 passing kernels.
// In must ALWAYS arrive as a pre-rounded value (load or earlier-rounded reg);
// never pass a fresh multiply (FMA contraction flips spikes — R8/R10).
// ---------------------------------------------------------------------------
__device__ __forceinline__ void izh_step(float In, float dtn, float dta,
                                         float bn, float cn, float dn, float thn,
                                         float& v, float& u, float& s)
{
    const float poly = 0.04f * v * v + 5.0f * v + 140.0f - u + In;
    const float vn = v + dtn * poly;
    const float un = u + dta * (bn * v - u);
    const bool  f  = (vn > thn);
    s = f ? 1.0f : 0.0f;
    v = f ? cn : vn;
    u = fmaf(dn, s, un);   // un + d*s, exact for s in {0,1}
}

// ---------------------------------------------------------------------------
// Kernel 2: per-neuron serial scan. TWO neurons per thread (adjacent n ->
// float2 I/O), 512 threads as 16 one-warp blocks (one warp per SM).
// PF=32 register prefetch: equilibrium memory cost latency/PF ~= 20 cyc/step
// even at DRAM-class latency (g_I gets evicted from L2 by the 96MB output
// stream — the R7/R11 ~125cyc/step bottleneck).
// 8192 % 32 == 0 -> exact main/tail split. Numerics identical to R11.
// ---------------------------------------------------------------------------
__global__ __launch_bounds__(32)
void scan_kernel(const float* __restrict__ st0,
                 const float* __restrict__ a_, const float* __restrict__ b_,
                 const float* __restrict__ c_, const float* __restrict__ d_,
                 const float* __restrict__ th_, const float* __restrict__ dt_,
                 float* __restrict__ spikes, float* __restrict__ states)
{
    const int p = blockIdx.x * 32 + threadIdx.x;   // 0..511
    const int n = 2 * p;

    float v0 = st0[n],      v1 = st0[n + 1];
    float u0 = st0[NN + n], u1 = st0[NN + n + 1];
    const float2 aa = *(const float2*)(a_  + n);
    const float2 bb = *(const float2*)(b_  + n);
    const float2 cc = *(const float2*)(c_  + n);
    const float2 dd = *(const float2*)(d_  + n);
    const float2 th = *(const float2*)(th_ + n);
    const float2 dt = *(const float2*)(dt_ + n);
    const float dta0 = dt.x * aa.x;
    const float dta1 = dt.y * aa.y;

    const float2* Ip = (const float2*)g_I + p;      // row stride NN/2
    float2* sp = (float2*)spikes + p;               // row stride NN/2
    float2* vp = (float2*)states + p;               // row stride NN
    float2* up = (float2*)states + (NN / 2) + p;

    constexpr int PF = 32;                          // deep pipeline (64 regs)
    float2 pf[PF];
    float s0, s1;

#pragma unroll
    for (int i = 0; i < PF; i++) pf[i] = Ip[(size_t)i * (NN / 2)];

#pragma unroll 1
    for (int t0 = 0; t0 < TSTEPS - PF; t0 += PF) {
#pragma unroll
        for (int k = 0; k < PF; k++) {
            const int t = t0 + k;
            const float2 In = pf[k];
            pf[k] = Ip[(size_t)(t + PF) * (NN / 2)];   // raw prefetch, no consumer

            izh_step(In.x, dt.x, dta0, bb.x, cc.x, dd.x, th.x, v0, u0, s0);
            izh_step(In.y, dt.y, dta1, bb.y, cc.y, dd.y, th.y, v1, u1, s1);

            sp[(size_t)t * (NN / 2)] = make_float2(s0, s1);
            vp[(size_t)t * NN]       = make_float2(v0, v1);
            up[(size_t)t * NN]       = make_float2(u0, u1);
        }
    }
#pragma unroll
    for (int k = 0; k < PF; k++) {
        const int t = TSTEPS - PF + k;
        const float2 In = pf[k];
        izh_step(In.x, dt.x, dta0, bb.x, cc.x, dd.x, th.x, v0, u0, s0);
        izh_step(In.y, dt.y, dta1, bb.y, cc.y, dd.y, th.y, v1, u1, s1);
        sp[(size_t)t * (NN / 2)] = make_float2(s0, s1);
        vp[(size_t)t * NN]       = make_float2(v0, v1);
        up[(size_t)t * NN]       = make_float2(u0, u1);
    }
}

// ---------------------------------------------------------------------------
// Kernel 3: S[t] = sum_n W2[n] * spikes[t,n]   (one block per timestep)
// ---------------------------------------------------------------------------
__global__ __launch_bounds__(256)
void rowsum_kernel(const float* __restrict__ spikes, const float* __restrict__ w2)
{
    const int t = blockIdx.x;
    const int tid = threadIdx.x;
    const float4 sv = ((const float4*)(spikes + (size_t)t * NN))[tid];
    const float4 wv = ((const float4*)w2)[tid];
    float sum = sv.x * wv.x + sv.y * wv.y + sv.z * wv.z + sv.w * wv.w;

#pragma unroll
    for (int o = 16; o > 0; o >>= 1)
        sum += __shfl_xor_sync(0xffffffffu, sum, o);

    __shared__ float ws[8];
    if ((tid & 31) == 0) ws[tid >> 5] = sum;
    __syncthreads();
    if (tid < 8) {
        float x = ws[tid];
#pragma unroll
        for (int o = 4; o > 0; o >>= 1)
            x += __shfl_xor_sync(0xffu, x, o);
        if (tid == 0) g_S[t] = x;
    }
}

// ---------------------------------------------------------------------------
// Kernel 4: parallel decode scan (affine composition, Hillis-Steele)
// ---------------------------------------------------------------------------
__global__ __launch_bounds__(1024)
void decode_scan_kernel(const float* __restrict__ leak,
                        float* __restrict__ decoded)
{
    constexpr int C = TSTEPS / 1024;   // 8
    __shared__ float s_scale[1024];
    __shared__ float s_off[1024];

    const int tid = threadIdx.x;
    const float L = leak[0];
    const int base = tid * C;

    float vals[C];
#pragma unroll
    for (int k = 0; k < C; k++) vals[k] = g_S[base + k];

    float dm = 0.f;
#pragma unroll
    for (int k = 0; k < C; k++) dm = L * dm + vals[k];
    float L2 = L * L, L4 = L2 * L2, L8 = L4 * L4;

    float myS = L8, myO = dm;
    s_scale[tid] = myS; s_off[tid] = myO;
    __syncthreads();

    for (int d = 1; d < 1024; d <<= 1) {
        float ps = 1.f, po = 0.f;
        if (tid >= d) { ps = s_scale[tid - d]; po = s_off[tid - d]; }
        __syncthreads();
        myO = myS * po + myO;
        myS = myS * ps;
        s_scale[tid] = myS; s_off[tid] = myO;
        __syncthreads();
    }

    const float carry_in = (tid == 0) ? 0.f : s_off[tid - 1];

    dm = carry_in;
#pragma unroll
    for (int k = 0; k < C; k++) {
        dm = L * dm + vals[k];
        decoded[base + k] = dm;
    }
}

// ---------------------------------------------------------------------------
extern "C" void kernel_launch(void* const* d_in, const int* in_sizes, int n_in,
                              void* d_out, int out_size)
{
    const float* X    = (const float*)d_in[0];   // [T, N]
    const float* st0  = (const float*)d_in[1];   // [2, N]
    const float* W1   = (const float*)d_in[2];   // [N, N]
    const float* W2   = (const float*)d_in[3];   // [1, N]
    const float* a    = (const float*)d_in[4];
    const float* b    = (const float*)d_in[5];
    const float* c    = (const float*)d_in[6];
    const float* d    = (const float*)d_in[7];
    const float* th   = (const float*)d_in[8];
    const float* dt   = (const float*)d_in[9];
    const float* leak = (const float*)d_in[10];

    float* out     = (float*)d_out;
    float* spikes  = out;                                       // [T, N]
    float* states  = out + (size_t)TSTEPS * NN;                 // [T, 2, N]
    float* decoded = out + (size_t)TSTEPS * NN * 3;             // [T, 1]

    // 0) W1 sparsity analysis
    analyze_kernel<<<NN / 8, 256>>>(W1);
    maxnnz_kernel<<<1, 256>>>();

    // 1) fill g_I: dense GEMM (dead when sparse) / sparse expand (dead when dense)
    dim3 ggrid(NN / 128, TSTEPS / 128);
    gemm_nt_kernel<<<ggrid, 256>>>(X, W1, TSTEPS, NN, NN);
    expand_kernel<<<TSTEPS, 256>>>(X);

    // 2) per-neuron scan: 2 neurons/thread, PF=32 deep prefetch
    scan_kernel<<<16, 32>>>(st0, a, b, c, d, th, dt, spikes, states);

    // 3) per-step weighted spike sums
    rowsum_kernel<<<TSTEPS, 256>>>(spikes, W2);

    // 4) decode leaky integrator (parallel affine scan)
    decode_scan_kernel<<<1, 1024>>>(leak, decoded);
}

// round 13
// speedup vs baseline: 3.3843x; 1.0124x over previous
#include <cuda_runtime.h>
#include <cuda_bf16.h>
#include <cstdint>

#define TSTEPS 8192
#define NN     1024

// Scratch (device globals; no allocation allowed in kernel_launch)
__device__ float g_I[(size_t)TSTEPS * NN];   // I_all = X @ W1^T (GEMM or expand)
__device__ float g_S[TSTEPS];                // per-step weighted spike sum
__device__ int   g_cnt[NN];                  // nonzeros per W1 row
__device__ __align__(16) int   g_col[NN];    // col of the single nonzero (if nnz<=1)
__device__ __align__(16) float g_val[NN];    // val of the single nonzero
__device__ int   g_maxnnz;                   // max row nnz; <=1 -> sparse fast path

// ---------------------------------------------------------------------------
// Packed fp32x2 helpers (Blackwell FFMA2)
// ---------------------------------------------------------------------------
__device__ __forceinline__ unsigned long long pack_dup(float x) {
    unsigned long long r;
    asm("mov.b64 %0, {%1, %1};" : "=l"(r) : "f"(x));
    return r;
}
__device__ __forceinline__ void ffma2(unsigned long long& d,
                                      unsigned long long a,
                                      unsigned long long b) {
    asm("fma.rn.f32x2 %0, %1, %2, %0;" : "+l"(d) : "l"(a), "l"(b));
}

// ---------------------------------------------------------------------------
// Kernel 0a: analyze W1 sparsity. One warp per row.
// ---------------------------------------------------------------------------
__global__ __launch_bounds__(256)
void analyze_kernel(const float* __restrict__ W1)
{
    const int warp = (blockIdx.x * blockDim.x + threadIdx.x) >> 5;
    const int lane = threadIdx.x & 31;
    if (warp >= NN) return;
    const float* row = W1 + (size_t)warp * NN;

    int   cnt = 0, col = 0;
    float val = 0.f;
#pragma unroll 4
    for (int c = lane; c < NN; c += 32) {
        float w = row[c];
        if (w != 0.f) { cnt++; col = c; val = w; }
    }
    int total = cnt;
#pragma unroll
    for (int o = 16; o > 0; o >>= 1)
        total += __shfl_xor_sync(0xffffffffu, total, o);
    unsigned mask = __ballot_sync(0xffffffffu, cnt > 0);
    int src = (mask != 0u) ? (__ffs(mask) - 1) : 0;
    col = __shfl_sync(0xffffffffu, col, src);
    val = __shfl_sync(0xffffffffu, val, src);
    if (lane == 0) {
        g_cnt[warp] = total;
        g_col[warp] = (mask != 0u) ? col : 0;
        g_val[warp] = (mask != 0u) ? val : 0.f;
    }
}

// ---------------------------------------------------------------------------
// Kernel 0b: g_maxnnz = max(g_cnt)
// ---------------------------------------------------------------------------
__global__ __launch_bounds__(256)
void maxnnz_kernel()
{
    const int tid = threadIdx.x;
    int m = 0;
#pragma unroll
    for (int i = tid; i < NN; i += 256) m = max(m, g_cnt[i]);
#pragma unroll
    for (int o = 16; o > 0; o >>= 1)
        m = max(m, __shfl_xor_sync(0xffffffffu, m, o));
    __shared__ int ws[8];
    if ((tid & 31) == 0) ws[tid >> 5] = m;
    __syncthreads();
    if (tid < 8) {
        int x = ws[tid];
#pragma unroll
        for (int o = 4; o > 0; o >>= 1)
            x = max(x, __shfl_xor_sync(0xffu, x, o));
        if (tid == 0) g_maxnnz = x;
    }
}

// ---------------------------------------------------------------------------
// Kernel 1 (dense fallback): C = A * B^T. Early-exits when W1 is 1-sparse.
// ---------------------------------------------------------------------------
__global__ __launch_bounds__(256, 2)
void gemm_nt_kernel(const float* __restrict__ A, const float* __restrict__ B,
                    int M, int N, int K)
{
    if (g_maxnnz <= 1) return;   // sparse fast path active -> dead launch

    constexpr int TM = 128, TN = 128, TK = 16;
    __shared__ float As[2][TK][TM + 4];
    __shared__ float Bs[2][TK][TN + 4];

    const int tid = threadIdx.x;
    const int bm = blockIdx.y * TM;
    const int bn = blockIdx.x * TN;

    const int lr = tid >> 2;
    const int lk = (tid & 3) * 4;

    const float* Ag = A + (size_t)(bm + lr) * K + lk;
    const float* Bg = B + (size_t)(bn + lr) * K + lk;

    const int tm = (tid >> 4) * 8;
    const int tn = (tid & 15) * 8;

    unsigned long long acc[8][4];
#pragma unroll
    for (int i = 0; i < 8; i++)
#pragma unroll
        for (int j = 0; j < 4; j++) acc[i][j] = 0ull;

    {
        float4 a0 = *(const float4*)(Ag);
        float4 a1 = *(const float4*)(Ag + (size_t)64 * K);
        float4 b0 = *(const float4*)(Bg);
        float4 b1 = *(const float4*)(Bg + (size_t)64 * K);
        As[0][lk + 0][lr]      = a0.x; As[0][lk + 1][lr]      = a0.y;
        As[0][lk + 2][lr]      = a0.z; As[0][lk + 3][lr]      = a0.w;
        As[0][lk + 0][lr + 64] = a1.x; As[0][lk + 1][lr + 64] = a1.y;
        As[0][lk + 2][lr + 64] = a1.z; As[0][lk + 3][lr + 64] = a1.w;
        Bs[0][lk + 0][lr]      = b0.x; Bs[0][lk + 1][lr]      = b0.y;
        Bs[0][lk + 2][lr]      = b0.z; Bs[0][lk + 3][lr]      = b0.w;
        Bs[0][lk + 0][lr + 64] = b1.x; Bs[0][lk + 1][lr + 64] = b1.y;
        Bs[0][lk + 2][lr + 64] = b1.z; Bs[0][lk + 3][lr + 64] = b1.w;
    }
    __syncthreads();

    int buf = 0;
#pragma unroll 1
    for (int kt = TK; kt <= K; kt += TK) {
        const bool last = (kt == K);
        float4 na0, na1, nb0, nb1;
        if (!last) {
            na0 = *(const float4*)(Ag + kt);
            na1 = *(const float4*)(Ag + (size_t)64 * K + kt);
            nb0 = *(const float4*)(Bg + kt);
            nb1 = *(const float4*)(Bg + (size_t)64 * K + kt);
        }

#pragma unroll
        for (int k = 0; k < TK; k++) {
            float4 af0 = *(const float4*)&As[buf][k][tm];
            float4 af1 = *(const float4*)&As[buf][k][tm + 4];
            ulonglong2 bq0 = *(const ulonglong2*)&Bs[buf][k][tn];
            ulonglong2 bq1 = *(const ulonglong2*)&Bs[buf][k][tn + 4];
            unsigned long long br[4] = {bq0.x, bq0.y, bq1.x, bq1.y};
            float ar[8] = {af0.x, af0.y, af0.z, af0.w,
                           af1.x, af1.y, af1.z, af1.w};
#pragma unroll
            for (int i = 0; i < 8; i++) {
                const unsigned long long ad = pack_dup(ar[i]);
#pragma unroll
                for (int j = 0; j < 4; j++)
                    ffma2(acc[i][j], ad, br[j]);
            }
        }

        if (!last) {
            const int nb = buf ^ 1;
            As[nb][lk + 0][lr]      = na0.x; As[nb][lk + 1][lr]      = na0.y;
            As[nb][lk + 2][lr]      = na0.z; As[nb][lk + 3][lr]      = na0.w;
            As[nb][lk + 0][lr + 64] = na1.x; As[nb][lk + 1][lr + 64] = na1.y;
            As[nb][lk + 2][lr + 64] = na1.z; As[nb][lk + 3][lr + 64] = na1.w;
            Bs[nb][lk + 0][lr]      = nb0.x; Bs[nb][lk + 1][lr]      = nb0.y;
            Bs[nb][lk + 2][lr]      = nb0.z; Bs[nb][lk + 3][lr]      = nb0.w;
            Bs[nb][lk + 0][lr + 64] = nb1.x; Bs[nb][lk + 1][lr + 64] = nb1.y;
            Bs[nb][lk + 2][lr + 64] = nb1.z; Bs[nb][lk + 3][lr + 64] = nb1.w;
            __syncthreads();
            buf = nb;
        }
    }

#pragma unroll
    for (int i = 0; i < 8; i++) {
        float* Cr = g_I + (size_t)(bm + tm + i) * N + bn + tn;
        ulonglong2 w0; w0.x = acc[i][0]; w0.y = acc[i][1];
        ulonglong2 w1; w1.x = acc[i][2]; w1.y = acc[i][3];
        *(ulonglong2*)(Cr)     = w0;
        *(ulonglong2*)(Cr + 4) = w1;
    }
}

// ---------------------------------------------------------------------------
// Kernel 1b (sparse path): g_I[t,n] = val[n] * X[t, col[n]].
// __fmul_rn = one explicit rounding, bit-identical to the GEMM's
// fma(x, w, 0) single-nonzero sum; cannot be FMA-contracted.
// ---------------------------------------------------------------------------
__global__ __launch_bounds__(256)
void expand_kernel(const float* __restrict__ X)
{
    if (g_maxnnz > 1) return;    // dense fallback active -> dead launch
    const int t  = blockIdx.x;
    const int n0 = threadIdx.x * 4;
    const float* Xr = X + (size_t)t * NN;
    const int4   c = *(const int4*)(g_col + n0);
    const float4 w = *(const float4*)(g_val + n0);
    float4 o;
    o.x = __fmul_rn(w.x, Xr[c.x]);
    o.y = __fmul_rn(w.y, Xr[c.y]);
    o.z = __fmul_rn(w.z, Xr[c.z]);
    o.w = __fmul_rn(w.w, Xr[c.w]);
    *(float4*)(g_I + (size_t)t * NN + n0) = o;
}

// ---------------------------------------------------------------------------
// Izhikevich Euler step — verbatim numerics of the R4/R11/R12 passing kernels.
// In must ALWAYS arrive as a pre-rounded value (load or earlier-rounded reg);
// never pass a fresh multiply (FMA contraction flips spikes — R8/R10).
// ---------------------------------------------------------------------------
__device__ __forceinline__ void izh_step(float In, float dtn, float dta,
                                         float bn, float cn, float dn, float thn,
                                         float& v, float& u, float& s)
{
    const float poly = 0.04f * v * v + 5.0f * v + 140.0f - u + In;
    const float vn = v + dtn * poly;
    const float un = u + dta * (bn * v - u);
    const bool  f  = (vn > thn);
    s = f ? 1.0f : 0.0f;
    v = f ? cn : vn;
    u = fmaf(dn, s, un);   // un + d*s, exact for s in {0,1}
}

// ---------------------------------------------------------------------------
// Kernel 2: per-neuron serial scan. ONE neuron per thread, 1024 threads as
// 32 one-warp blocks (one warp per SM, 32 SMs). Warps are independent, so
// wall time = per-warp issue per step; 1n/thread minimizes it (~44 cyc model
// vs 61 measured at 2n/thread). PF=32 scalar prefetch keeps memory cost at
// latency/32. Bit-identical per-neuron arithmetic and data vs R12.
// ---------------------------------------------------------------------------
__global__ __launch_bounds__(32)
void scan_kernel(const float* __restrict__ st0,
                 const float* __restrict__ a_, const float* __restrict__ b_,
                 const float* __restrict__ c_, const float* __restrict__ d_,
                 const float* __restrict__ th_, const float* __restrict__ dt_,
                 float* __restrict__ spikes, float* __restrict__ states)
{
    const int n = blockIdx.x * 32 + threadIdx.x;   // 0..1023

    float v = st0[n];
    float u = st0[NN + n];
    const float an  = a_[n],  bn  = b_[n];
    const float cn  = c_[n],  dn  = d_[n];
    const float thn = th_[n], dtn = dt_[n];
    const float dta = dtn * an;

    const float* Ip = g_I + n;       // stride NN
    float* sp = spikes + n;          // stride NN
    float* vp = states + n;          // stride 2*NN
    float* up = states + NN + n;

    constexpr int PF = 32;           // deep pipeline: 32 outstanding LDG.32
    float pf[PF];
    float s;

#pragma unroll
    for (int i = 0; i < PF; i++) pf[i] = Ip[(size_t)i * NN];

#pragma unroll 1
    for (int t0 = 0; t0 < TSTEPS - PF; t0 += PF) {   // 255 iterations
#pragma unroll
        for (int k = 0; k < PF; k++) {
            const int t = t0 + k;
            const float In = pf[k];
            pf[k] = Ip[(size_t)(t + PF) * NN];       // raw prefetch, no consumer

            izh_step(In, dtn, dta, bn, cn, dn, thn, v, u, s);

            sp[(size_t)t * NN]     = s;
            vp[(size_t)t * 2 * NN] = v;
            up[(size_t)t * 2 * NN] = u;
        }
    }
#pragma unroll
    for (int k = 0; k < PF; k++) {
        const int t = TSTEPS - PF + k;
        izh_step(pf[k], dtn, dta, bn, cn, dn, thn, v, u, s);
        sp[(size_t)t * NN]     = s;
        vp[(size_t)t * 2 * NN] = v;
        up[(size_t)t * 2 * NN] = u;
    }
}

// ---------------------------------------------------------------------------
// Kernel 3: S[t] = sum_n W2[n] * spikes[t,n].
// 4 timesteps per block (amortizes W2 loads + reduction setup).
// ---------------------------------------------------------------------------
__global__ __launch_bounds__(256)
void rowsum_kernel(const float* __restrict__ spikes, const float* __restrict__ w2)
{
    const int tid = threadIdx.x;
    const float4 wv = ((const float4*)w2)[tid];
    __shared__ float ws[8];

#pragma unroll
    for (int q = 0; q < 4; q++) {
        const int t = blockIdx.x * 4 + q;
        const float4 sv = ((const float4*)(spikes + (size_t)t * NN))[tid];
        float sum = sv.x * wv.x + sv.y * wv.y + sv.z * wv.z + sv.w * wv.w;

#pragma unroll
        for (int o = 16; o > 0; o >>= 1)
            sum += __shfl_xor_sync(0xffffffffu, sum, o);

        if ((tid & 31) == 0) ws[tid >> 5] = sum;
        __syncthreads();
        if (tid < 8) {
            float x = ws[tid];
#pragma unroll
            for (int o = 4; o > 0; o >>= 1)
                x += __shfl_xor_sync(0xffu, x, o);
            if (tid == 0) g_S[t] = x;
        }
        __syncthreads();
    }
}

// ---------------------------------------------------------------------------
// Kernel 4: parallel decode scan (affine composition, Hillis-Steele)
// ---------------------------------------------------------------------------
__global__ __launch_bounds__(1024)
void decode_scan_kernel(const float* __restrict__ leak,
                        float* __restrict__ decoded)
{
    constexpr int C = TSTEPS / 1024;   // 8
    __shared__ float s_scale[1024];
    __shared__ float s_off[1024];

    const int tid = threadIdx.x;
    const float L = leak[0];
    const int base = tid * C;

    float vals[C];
#pragma unroll
    for (int k = 0; k < C; k++) vals[k] = g_S[base + k];

    float dm = 0.f;
#pragma unroll
    for (int k = 0; k < C; k++) dm = L * dm + vals[k];
    float L2 = L * L, L4 = L2 * L2, L8 = L4 * L4;

    float myS = L8, myO = dm;
    s_scale[tid] = myS; s_off[tid] = myO;
    __syncthreads();

    for (int d = 1; d < 1024; d <<= 1) {
        float ps = 1.f, po = 0.f;
        if (tid >= d) { ps = s_scale[tid - d]; po = s_off[tid - d]; }
        __syncthreads();
        myO = myS * po + myO;
        myS = myS * ps;
        s_scale[tid] = myS; s_off[tid] = myO;
        __syncthreads();
    }

    const float carry_in = (tid == 0) ? 0.f : s_off[tid - 1];

    dm = carry_in;
#pragma unroll
    for (int k = 0; k < C; k++) {
        dm = L * dm + vals[k];
        decoded[base + k] = dm;
    }
}

// ---------------------------------------------------------------------------
extern "C" void kernel_launch(void* const* d_in, const int* in_sizes, int n_in,
                              void* d_out, int out_size)
{
    const float* X    = (const float*)d_in[0];   // [T, N]
    const float* st0  = (const float*)d_in[1];   // [2, N]
    const float* W1   = (const float*)d_in[2];   // [N, N]
    const float* W2   = (const float*)d_in[3];   // [1, N]
    const float* a    = (const float*)d_in[4];
    const float* b    = (const float*)d_in[5];
    const float* c    = (const float*)d_in[6];
    const float* d    = (const float*)d_in[7];
    const float* th   = (const float*)d_in[8];
    const float* dt   = (const float*)d_in[9];
    const float* leak = (const float*)d_in[10];

    float* out     = (float*)d_out;
    float* spikes  = out;                                       // [T, N]
    float* states  = out + (size_t)TSTEPS * NN;                 // [T, 2, N]
    float* decoded = out + (size_t)TSTEPS * NN * 3;             // [T, 1]

    // 0) W1 sparsity analysis
    analyze_kernel<<<NN / 8, 256>>>(W1);
    maxnnz_kernel<<<1, 256>>>();

    // 1) fill g_I: dense GEMM (dead when sparse) / sparse expand (dead when dense)
    dim3 ggrid(NN / 128, TSTEPS / 128);
    gemm_nt_kernel<<<ggrid, 256>>>(X, W1, TSTEPS, NN, NN);
    expand_kernel<<<TSTEPS, 256>>>(X);

    // 2) per-neuron scan: 1 neuron/thread, 32 one-warp blocks, PF=32
    scan_kernel<<<32, 32>>>(st0, a, b, c, d, th, dt, spikes, states);

    // 3) per-step weighted spike sums (4 timesteps per block)
    rowsum_kernel<<<TSTEPS / 4, 256>>>(spikes, W2);

    // 4) decode leaky integrator (parallel affine scan)
    decode_scan_kernel<<<1, 1024>>>(leak, decoded);
}